// round 17
// baseline (speedup 1.0000x reference)
#include <cuda_runtime.h>
#include <cstdint>
#include <cstddef>

// Problem shapes (fixed per metadata)
#define B_ 8
#define K_ 1024
#define L_ 1024
#define D_ 1024
#define O_ 6
#define E_ 128
#define KS_ 16                 // k-split for u-sum partials
#define KT_ 32                 // k tile per pass unit
#define NBLK_K (K_/KT_)        // 32
#define VPS_ 256               // vpart storage slots per o
#define BN_ 296                // persistent grid: 2 blocks per SM (148 SMs)
#define T_ 256

// ---------------- scratch (device globals; no allocation allowed) ----------------
__device__ __align__(16) float g_us_part[B_*KS_*D_];
__device__ __align__(16) float g_w[B_*O_*D_];
__device__ __align__(16) float g_logits[B_*K_*O_];
__device__ __align__(16) float g_probs[B_*K_*O_];
__device__ __align__(16) float g_t_part[(size_t)B_*NBLK_K*O_*D_];   // 6.3MB
__device__ __align__(16) float g_vpart[O_][VPS_][B_][E_];           // 6.3MB
__device__ __align__(16) float g_v[B_*O_*E_];
__device__ unsigned char g_mask[B_*K_];

// barrier state: count self-resets; gen is monotone => replay-safe.
__device__ unsigned g_bar_cnt = 0;
__device__ volatile unsigned g_bar_gen = 0;

__device__ __forceinline__ void grid_barrier() {
    __syncthreads();
    __threadfence();                       // every thread flushes its writes
    if (threadIdx.x == 0) {
        unsigned snap = g_bar_gen;
        unsigned a = atomicAdd(&g_bar_cnt, 1u);
        if (a == BN_ - 1u) {
            g_bar_cnt = 0;
            __threadfence();
            g_bar_gen = snap + 1u;
        } else {
            while ((int)(g_bar_gen - snap) <= 0) __nanosleep(64);
        }
    }
    __syncthreads();
}

// ---------------- shared memory union across phases ----------------
struct SPass { float w[O_*D_]; float p[KT_][O_]; };          // 25344 B
struct SVpart { float red[64][4]; float st[B_][8]; };
struct SVcomb { float part[2][E_]; float sv[E_]; float ssq; };
struct SW { float4 sv4[B_][E_/4]; };
union __align__(16) USm {
    SPass pass;
    SVpart vp;
    SVcomb vc;
    SW w;
    int flag;
};

// ---------------- phase: v partials (t-reduction fused) ----------------
__device__ __forceinline__ void phase_vpart(int use_t, const float* __restrict__ W,
                                            USm& sm) {
    int tid = threadIdx.x;
    for (int v = blockIdx.x; v < 768; v += BN_) {
        int o = v >> 7; int dsl = v & 127; int d0 = dsl * 8;
        {
            int entry = tid >> 2, sub = tid & 3;
            int b = entry >> 3, dd = entry & 7;
            float s = 0.f;
            if (use_t) {
                const float* p = g_t_part + ((size_t)(b*NBLK_K*O_ + o))*D_ + d0 + dd;
                #pragma unroll
                for (int j = sub; j < NBLK_K; j += 4) s += __ldcg(p + (size_t)j*O_*D_);
            } else {
                const float* p = g_us_part + (size_t)b*KS_*D_ + d0 + dd;
                #pragma unroll
                for (int j = sub; j < KS_; j += 4) s += __ldcg(p + (size_t)j*D_);
            }
            sm.vp.red[entry][sub] = s;
        }
        __syncthreads();
        if (tid < 64) {
            sm.vp.st[tid >> 3][tid & 7] =
                sm.vp.red[tid][0] + sm.vp.red[tid][1] + sm.vp.red[tid][2] + sm.vp.red[tid][3];
        }
        __syncthreads();
        int e = tid & 127, h = tid >> 7;
        const float* Wo = W + ((size_t)(o*D_ + d0 + h*4))*E_ + e;
        float acc[B_];
        #pragma unroll
        for (int b = 0; b < B_; ++b) acc[b] = 0.f;
        #pragma unroll
        for (int dd = 0; dd < 4; ++dd) {
            float wv = Wo[(size_t)dd*E_];
            #pragma unroll
            for (int b = 0; b < B_; ++b) acc[b] += wv * sm.vp.st[b][h*4 + dd];
        }
        #pragma unroll
        for (int b = 0; b < B_; ++b) g_vpart[o][dsl*2 + h][b][e] = acc[b];
        __syncthreads();
    }
}

// ---------------- phase: combine partials + squash -> g_v ----------------
__device__ __forceinline__ void phase_vcomb(float scale, USm& sm) {
    int tid = threadIdx.x;
    int v = blockIdx.x;
    if (v < B_*O_) {
        int b = v / O_, o = v % O_;
        int e = tid & 127, q = tid >> 7;
        float s = 0.f;
        #pragma unroll 16
        for (int s2 = q; s2 < VPS_; s2 += 2) s += __ldcg(&g_vpart[o][s2][b][e]);
        sm.vc.part[q][e] = s;
        __syncthreads();
        if (q == 0) sm.vc.sv[e] = (sm.vc.part[0][e] + sm.vc.part[1][e]) * scale;
        __syncthreads();
        if (tid < 32) {
            float x0 = sm.vc.sv[tid],      x1 = sm.vc.sv[tid+32],
                  x2 = sm.vc.sv[tid+64],   x3 = sm.vc.sv[tid+96];
            float s2 = x0*x0 + x1*x1 + x2*x2 + x3*x3;
            #pragma unroll
            for (int off = 16; off; off >>= 1) s2 += __shfl_xor_sync(0xffffffffu, s2, off);
            if (tid == 0) sm.vc.ssq = s2;
        }
        __syncthreads();
        if (q == 0) {
            float sq = sm.vc.ssq;
            float factor = sq / (1.f + sq) / (sqrtf(sq) + 1e-8f);
            g_v[(size_t)v*E_ + e] = sm.vc.sv[e] * factor;
        }
    }
}

// ---------------- phase: w[b,o,d] = sum_e W[o,d,e] * v[b,o,e] ----------------
__device__ __forceinline__ void phase_w(const float* __restrict__ W, USm& sm) {
    int tid = threadIdx.x;
    for (int v = blockIdx.x; v < 768; v += BN_) {
        int o = v >> 7; int dgrp = v & 127;
        {   // stage v (all batches of this o) as float4
            int b = tid >> 5, l = tid & 31;
            const float4* src = (const float4*)(g_v + ((size_t)(b*O_ + o))*E_);
            sm.w.sv4[b][l] = __ldcg(src + l);
        }
        __syncthreads();
        int wid = tid >> 5, lane = tid & 31;
        int d = dgrp*8 + wid;
        const float4* Wr = (const float4*)(W + ((size_t)(o*D_ + d))*E_);
        float4 wq = Wr[lane];
        float a[B_];
        #pragma unroll
        for (int b = 0; b < B_; ++b) {
            float4 c = sm.w.sv4[b][lane];
            a[b] = wq.x*c.x + wq.y*c.y + wq.z*c.z + wq.w*c.w;
        }
        #pragma unroll
        for (int b = 0; b < B_; ++b) {
            #pragma unroll
            for (int off = 16; off; off >>= 1)
                a[b] += __shfl_xor_sync(0xffffffffu, a[b], off);
        }
        if (lane == 0) {
            #pragma unroll
            for (int b = 0; b < B_; ++b)
                g_w[((size_t)(b*O_ + o))*D_ + d] = a[b];
        }
        __syncthreads();
    }
}

// ---------------- phase: fused routing pass ----------------
__device__ __forceinline__ void phase_pass(const float* __restrict__ u, int iter3,
                                           USm& sm) {
    int tid = threadIdx.x;
    for (int v = blockIdx.x; v < NBLK_K*B_; v += BN_) {
        int kblk = v & (NBLK_K-1);
        int b = v >> 5;
        int k0 = kblk * KT_;
        const float* wb = g_w + (size_t)b*O_*D_;
        for (int i = tid; i < O_*D_; i += T_) sm.pass.w[i] = __ldcg(wb + i);
        __syncthreads();
        int warp = tid >> 5, lane = tid & 31;
        for (int kk = warp; kk < KT_; kk += 8) {
            int k = k0 + kk;
            const float* ur = u + ((size_t)(b*K_ + k))*D_;
            float a0=0,a1=0,a2=0,a3=0,a4=0,a5=0;
            #pragma unroll
            for (int j = 0; j < D_/32; ++j) {
                int d = j*32 + lane;
                float uv = ur[d];
                a0 += uv * sm.pass.w[0*D_+d];
                a1 += uv * sm.pass.w[1*D_+d];
                a2 += uv * sm.pass.w[2*D_+d];
                a3 += uv * sm.pass.w[3*D_+d];
                a4 += uv * sm.pass.w[4*D_+d];
                a5 += uv * sm.pass.w[5*D_+d];
            }
            #pragma unroll
            for (int off = 16; off; off >>= 1) {
                a0 += __shfl_xor_sync(0xffffffffu, a0, off);
                a1 += __shfl_xor_sync(0xffffffffu, a1, off);
                a2 += __shfl_xor_sync(0xffffffffu, a2, off);
                a3 += __shfl_xor_sync(0xffffffffu, a3, off);
                a4 += __shfl_xor_sync(0xffffffffu, a4, off);
                a5 += __shfl_xor_sync(0xffffffffu, a5, off);
            }
            int base = (b*K_ + k)*O_;
            if (iter3) {
                a0 += g_logits[base+0]; a1 += g_logits[base+1];
                a2 += g_logits[base+2]; a3 += g_logits[base+3];
                a4 += g_logits[base+4]; a5 += g_logits[base+5];
            } else if (lane < O_) {
                float sv = a0;
                if (lane==1) sv=a1; else if (lane==2) sv=a2; else if (lane==3) sv=a3;
                else if (lane==4) sv=a4; else if (lane==5) sv=a5;
                g_logits[base+lane] = sv;
            }
            float m = fmaxf(fmaxf(fmaxf(a0,a1),fmaxf(a2,a3)),fmaxf(a4,a5));
            float e0=__expf(a0-m), e1=__expf(a1-m), e2=__expf(a2-m),
                  e3=__expf(a3-m), e4=__expf(a4-m), e5=__expf(a5-m);
            float s = e0+e1+e2+e3+e4+e5;
            bool msk = (g_mask[b*K_ + k] != 0);
            float inv = msk ? (1.0f/6.0f) : (1.0f/s);
            float p0 = msk?inv:e0*inv, p1 = msk?inv:e1*inv, p2 = msk?inv:e2*inv;
            float p3 = msk?inv:e3*inv, p4 = msk?inv:e4*inv, p5 = msk?inv:e5*inv;
            if (lane < O_) {
                float pv = p0;
                if (lane==1) pv=p1; else if (lane==2) pv=p2; else if (lane==3) pv=p3;
                else if (lane==4) pv=p4; else if (lane==5) pv=p5;
                sm.pass.p[kk][lane] = pv;
                if (iter3) g_probs[base+lane] = pv;
            }
        }
        __syncthreads();
        // phase B: partial t[o,d] = sum_{k in tile} p[k,o] * u[b,k,d]
        float* tp = g_t_part + ((size_t)(b*NBLK_K + kblk))*O_*D_;
        const float* ub = u + ((size_t)(b*K_ + k0))*D_;
        #pragma unroll
        for (int r = 0; r < D_/T_; ++r) {
            int d = tid + T_*r;
            float t0=0,t1=0,t2=0,t3=0,t4=0,t5=0;
            #pragma unroll 8
            for (int kk = 0; kk < KT_; ++kk) {
                float uv = ub[(size_t)kk*D_ + d];   // hot in L1/L2 from phase A
                t0 += uv*sm.pass.p[kk][0]; t1 += uv*sm.pass.p[kk][1];
                t2 += uv*sm.pass.p[kk][2]; t3 += uv*sm.pass.p[kk][3];
                t4 += uv*sm.pass.p[kk][4]; t5 += uv*sm.pass.p[kk][5];
            }
            tp[0*D_+d]=t0; tp[1*D_+d]=t1; tp[2*D_+d]=t2;
            tp[3*D_+d]=t3; tp[4*D_+d]=t4; tp[5*D_+d]=t5;
        }
        __syncthreads();
    }
}

// ---------------- the persistent mega-kernel ----------------
__global__ void __launch_bounds__(T_, 2) mega(
    const float* __restrict__ u, const float* __restrict__ W,
    const void* __restrict__ rawmask,
    float4* __restrict__ outv, float4* __restrict__ outp) {
    __shared__ USm sm;
    int tid = threadIdx.x;

    // ---- P0: mask ingest (blocks 0..7) + u-sum split-K partials ----
    if (blockIdx.x < B_) {
        if (tid == 0) sm.flag = 0;
        __syncthreads();
        const unsigned int* w32 = (const unsigned int*)rawmask;
        int f = 0;
        for (int i = tid; i < (B_*K_)/4; i += T_)
            if (w32[i] > 1u) f = 1;          // packed-byte pattern > 1
        if (f) atomicOr(&sm.flag, 1);
        __syncthreads();
        int isbyte = sm.flag;
        const unsigned char* b8 = (const unsigned char*)rawmask;
        int b = blockIdx.x;
        for (int i = tid; i < K_; i += T_) {
            int idx = b*K_ + i;
            unsigned char m = isbyte ? b8[idx] : (unsigned char)(w32[idx] != 0u);
            g_mask[idx] = m ? (unsigned char)1 : (unsigned char)0;
        }
    }
    for (int v = blockIdx.x; v < B_*KS_*(D_/T_); v += BN_) {   // 512 units
        int b = v >> 6; int ks = (v >> 2) & 15; int dc = v & 3;
        int d = dc*T_ + tid;
        const float* up = u + ((size_t)(b*K_ + ks*(K_/KS_)))*D_ + d;
        float s = 0.f;
        #pragma unroll 8
        for (int k = 0; k < K_/KS_; ++k) s += up[(size_t)k*D_];
        g_us_part[((size_t)(b*KS_ + ks))*D_ + d] = s;
    }
    grid_barrier();

    // ---- iteration 1 ----
    phase_vpart(0, W, sm);        grid_barrier();
    phase_vcomb(1.0f/6.0f, sm);   grid_barrier();
    phase_w(W, sm);               grid_barrier();

    // ---- iteration 2 ----
    phase_pass(u, 0, sm);         grid_barrier();
    phase_vpart(1, W, sm);        grid_barrier();
    phase_vcomb(1.0f, sm);        grid_barrier();
    phase_w(W, sm);               grid_barrier();

    // ---- iteration 3 ----
    phase_pass(u, 1, sm);         grid_barrier();
    phase_vpart(1, W, sm);        grid_barrier();
    phase_vcomb(1.0f, sm);        grid_barrier();

    // ---- P11: broadcast both outputs over L (full grid, pure write BW) ----
    {
        int gt = blockIdx.x*T_ + tid;
        const int GS = BN_*T_;
        const float4* sv = (const float4*)g_v;       // 1536 float4
        const int PV = O_*E_/4;                      // 192
        for (int i = gt; i < B_*L_*PV; i += GS) {
            int bl = i / PV; int j = i - bl*PV; int b = bl >> 10;
            __stcs(outv + i, __ldcg(sv + b*PV + j));
        }
        const float4* sp = (const float4*)g_probs;   // 12288 float4
        const int PP = K_*O_/4;                      // 1536
        for (int i = gt; i < B_*L_*PP; i += GS) {
            int bl = i / PP; int j = i - bl*PP; int b = bl >> 10;
            __stcs(outp + i, __ldcg(sp + b*PP + j));
        }
    }
}

// ---------------- launch ----------------
extern "C" void kernel_launch(void* const* d_in, const int* in_sizes, int n_in,
                              void* d_out, int out_size) {
    const float* u    = (const float*)d_in[0];   // inputs_u (B,K,D)
    // d_in[1] = context_sequence — unused by the math (shape only)
    const float* W    = (const float*)d_in[2];   // route_weights (O,D,E)
    const void*  mask = d_in[3];                 // inputs_mask (B,K)

    float* out   = (float*)d_out;
    float4* outv = (float4*)out;                                  // outputs_v (B,L,O,E)
    float4* outp = (float4*)(out + (size_t)B_*L_*O_*E_);          // probs_c   (B,L,K,O)

    mega<<<BN_, T_>>>(u, W, mask, outv, outp);
}